// round 11
// baseline (speedup 1.0000x reference)
#include <cuda_runtime.h>
#include <cuda_bf16.h>

#define WEIGHT_POSITIVE 0.1f

// Scratch (no device allocations allowed). Statically zero-initialized;
// the last block resets them after finalizing, so every graph replay
// starts from a clean state.
__device__ double       g_acc   = 0.0;
__device__ unsigned int g_count = 0;

__device__ __forceinline__ float elem_loss(float p, int t) {
    float tf = (float)t;
    float d  = p - tf;
    bool mis = (p >= 0.5f) != (t == 1);
    float w  = mis ? (1.0f + WEIGHT_POSITIVE) : 1.0f;
    return (w * d) * d;
}

__global__ __launch_bounds__(256, 8) void wmse_fused_kernel(
    const float4* __restrict__ pred4,
    const int4*   __restrict__ tgt4,
    int nvec,               // number of vec4 elements
    int iters,              // exact per-thread iterations (grid divides nvec)
    float* __restrict__ out,
    double inv_n)
{
    const int tid     = blockIdx.x * blockDim.x + threadIdx.x;
    const int nthread = gridDim.x * blockDim.x;

    float acc0 = 0.0f, acc1 = 0.0f;

    // Main body: exact trip count, no bounds checks, no tail.
    #pragma unroll 4
    for (int j = 0; j < iters; j++) {
        int i = tid + j * nthread;
        float4 p = __ldcs(&pred4[i]);
        int4   t = __ldcs(&tgt4[i]);
        acc0 += elem_loss(p.x, t.x);
        acc1 += elem_loss(p.y, t.y);
        acc0 += elem_loss(p.z, t.z);
        acc1 += elem_loss(p.w, t.w);
    }

    // Safety tail for non-dividing sizes (empty for N = 2^25).
    for (int i = tid + iters * nthread; i < nvec; i += nthread) {
        float4 p = __ldcs(&pred4[i]);
        int4   t = __ldcs(&tgt4[i]);
        acc0 += elem_loss(p.x, t.x);
        acc1 += elem_loss(p.y, t.y);
        acc0 += elem_loss(p.z, t.z);
        acc1 += elem_loss(p.w, t.w);
    }

    float local = acc0 + acc1;

    // Warp reduce.
    #pragma unroll
    for (int off = 16; off > 0; off >>= 1)
        local += __shfl_down_sync(0xFFFFFFFFu, local, off);

    __shared__ float warp_sums[8];  // 256 threads = 8 warps
    int lane = threadIdx.x & 31;
    int wid  = threadIdx.x >> 5;
    if (lane == 0) warp_sums[wid] = local;
    __syncthreads();

    __shared__ bool is_last;
    if (threadIdx.x == 0) {
        float v = 0.0f;
        #pragma unroll
        for (int k = 0; k < 8; k++) v += warp_sums[k];
        atomicAdd(&g_acc, (double)v);
        __threadfence();
        unsigned int ticket = atomicAdd(&g_count, 1u);
        is_last = (ticket == gridDim.x - 1);
    }
    __syncthreads();

    // Last block to arrive finalizes and resets state for the next replay.
    if (is_last && threadIdx.x == 0) {
        double total = g_acc;           // ordered by the ticket protocol
        out[0] = (float)(total * inv_n);
        g_acc   = 0.0;
        g_count = 0u;
        __threadfence();
    }
}

extern "C" void kernel_launch(void* const* d_in, const int* in_sizes, int n_in,
                              void* d_out, int out_size) {
    const float* pred = (const float*)d_in[0];
    const int*   tgt  = (const int*)d_in[1];
    float* out = (float*)d_out;
    int n    = in_sizes[0];
    int nvec = n >> 2;                 // n = 2^25 -> 8388608 vec4

    // 2048 blocks x 256 threads = 524288 threads: divides nvec exactly
    // (16 iters/thread, no tail work). Converged configuration: measured
    // at the chip streaming ceiling (~6.3 TB/s effective, LTS-cap bound).
    const int threads = 256;
    const int blocks  = 2048;
    const int nthread = blocks * threads;
    const int iters   = nvec / nthread;   // = 16 for n = 2^25

    wmse_fused_kernel<<<blocks, threads>>>(
        (const float4*)pred, (const int4*)tgt, nvec, iters, out,
        1.0 / (double)n);
}

// round 15
// speedup vs baseline: 1.0059x; 1.0059x over previous
#include <cuda_runtime.h>
#include <cuda_bf16.h>

#define WEIGHT_POSITIVE 0.1f

// Scratch (no device allocations allowed). Statically zero-initialized;
// the last block resets them after finalizing, so every graph replay
// starts from a clean state.
__device__ double       g_acc   = 0.0;
__device__ unsigned int g_count = 0;

__device__ __forceinline__ float elem_loss(float p, int t) {
    float tf = (float)t;
    float d  = p - tf;
    bool mis = (p >= 0.5f) != (t == 1);
    float w  = mis ? (1.0f + WEIGHT_POSITIVE) : 1.0f;
    return (w * d) * d;
}

__global__ __launch_bounds__(256, 8) void wmse_fused_kernel(
    const float4* __restrict__ pred4,
    const int4*   __restrict__ tgt4,
    int nvec,               // number of vec4 elements
    int iters,              // exact per-thread iterations (grid divides nvec)
    float* __restrict__ out,
    double inv_n)
{
    const int tid     = blockIdx.x * blockDim.x + threadIdx.x;
    const int nthread = gridDim.x * blockDim.x;

    float acc0 = 0.0f, acc1 = 0.0f;

    // Main body: exact trip count, no bounds checks, no tail.
    #pragma unroll 4
    for (int j = 0; j < iters; j++) {
        int i = tid + j * nthread;
        float4 p = __ldcs(&pred4[i]);
        int4   t = __ldcs(&tgt4[i]);
        acc0 += elem_loss(p.x, t.x);
        acc1 += elem_loss(p.y, t.y);
        acc0 += elem_loss(p.z, t.z);
        acc1 += elem_loss(p.w, t.w);
    }

    // Safety tail for non-dividing sizes (empty for N = 2^25).
    for (int i = tid + iters * nthread; i < nvec; i += nthread) {
        float4 p = __ldcs(&pred4[i]);
        int4   t = __ldcs(&tgt4[i]);
        acc0 += elem_loss(p.x, t.x);
        acc1 += elem_loss(p.y, t.y);
        acc0 += elem_loss(p.z, t.z);
        acc1 += elem_loss(p.w, t.w);
    }

    float local = acc0 + acc1;

    // Warp reduce.
    #pragma unroll
    for (int off = 16; off > 0; off >>= 1)
        local += __shfl_down_sync(0xFFFFFFFFu, local, off);

    __shared__ float warp_sums[8];  // 256 threads = 8 warps
    int lane = threadIdx.x & 31;
    int wid  = threadIdx.x >> 5;
    if (lane == 0) warp_sums[wid] = local;
    __syncthreads();

    __shared__ bool is_last;
    if (threadIdx.x == 0) {
        float v = 0.0f;
        #pragma unroll
        for (int k = 0; k < 8; k++) v += warp_sums[k];
        atomicAdd(&g_acc, (double)v);
        __threadfence();
        unsigned int ticket = atomicAdd(&g_count, 1u);
        is_last = (ticket == gridDim.x - 1);
    }
    __syncthreads();

    // Last block to arrive finalizes and resets state for the next replay.
    if (is_last && threadIdx.x == 0) {
        double total = g_acc;           // ordered by the ticket protocol
        out[0] = (float)(total * inv_n);
        g_acc   = 0.0;
        g_count = 0u;
        __threadfence();
    }
}

extern "C" void kernel_launch(void* const* d_in, const int* in_sizes, int n_in,
                              void* d_out, int out_size) {
    const float* pred = (const float*)d_in[0];
    const int*   tgt  = (const int*)d_in[1];
    float* out = (float*)d_out;
    int n    = in_sizes[0];
    int nvec = n >> 2;                 // n = 2^25 -> 8388608 vec4

    // 2048 blocks x 256 threads = 524288 threads: divides nvec exactly
    // (16 iters/thread, no tail work). Converged configuration: measured
    // at the chip streaming ceiling (~6.3 TB/s effective, LTS-cap bound).
    const int threads = 256;
    const int blocks  = 2048;
    const int nthread = blocks * threads;
    const int iters   = nvec / nthread;   // = 16 for n = 2^25

    wmse_fused_kernel<<<blocks, threads>>>(
        (const float4*)pred, (const int4*)tgt, nvec, iters, out,
        1.0 / (double)n);
}